// round 1
// baseline (speedup 1.0000x reference)
#include <cuda_runtime.h>
#include <math.h>

#define B_   64
#define S_   512
#define P_   32
#define L_   30
#define H_   768
#define FH_  1024
#define MROWS (B_*P_)   // 2048

// ---------------- scratch (device globals; no allocation) ----------------
__device__ float g_pp[B_ * FH_];            // pooler @ W1[768:] + b1   [64,1024]
__device__ float g_h1[MROWS * FH_];         // [2048,1024]
__device__ float g_h2[MROWS * (FH_ / 2)];   // [2048,512]
__device__ int   g_rowoff[MROWS];           // gather offsets into token_embeddings
__device__ float g_part[256 * 5];           // per-block loss partials

// ---------------- gather offset precompute ----------------
__global__ void k_rowoff(const int* __restrict__ pos) {
    int r = blockIdx.x * blockDim.x + threadIdx.x;
    if (r < MROWS) {
        int b = r >> 5;                       // P_ = 32
        g_rowoff[r] = (b * S_ + pos[r]) * H_;
    }
}

// ---------------- fp32 register-tiled SGEMM ----------------
// C[M,N] = A[M,K] @ B[K,N] (+bias[N]) (+perRow[(row>>5)*N + col])
// A rows optionally gathered via arow[] (element offsets into A).
// BM=128, BN=128, BK=8, TM=TN=8, 256 threads. N must be multiple of 128,
// K multiple of 8; M arbitrary (guarded).
__global__ __launch_bounds__(256)
void sgemm128(const float* __restrict__ A, const int* __restrict__ arow,
              const float* __restrict__ Bm, float* __restrict__ C,
              int M, int N, int K,
              const float* __restrict__ bias,
              const float* __restrict__ perRow)
{
    const int BM = 128, BN = 128, BK = 8, TM = 8, TN = 8;
    __shared__ float As[BK][BM];
    __shared__ float Bs[BK][BN];

    const int tid = threadIdx.x;
    const int tx = tid % (BN / TN);           // 0..15
    const int ty = tid / (BN / TN);           // 0..15
    const int rowBase = blockIdx.y * BM;
    const int colBase = blockIdx.x * BN;

    // A tile load: 128 rows x 8 k  -> 256 float4
    const int aRow = tid >> 1;                 // 0..127
    const int aCol = (tid & 1) * 4;            // 0 or 4
    // B tile load: 8 k x 128 cols -> 256 float4
    const int bRow = tid >> 5;                 // 0..7
    const int bCol = (tid & 31) * 4;           // 0..124

    const int aGRow = rowBase + aRow;
    long aBase = -1;
    if (aGRow < M) aBase = arow ? (long)arow[aGRow] : (long)aGRow * K;

    float acc[TM][TN];
#pragma unroll
    for (int i = 0; i < TM; i++)
#pragma unroll
        for (int j = 0; j < TN; j++) acc[i][j] = 0.f;

    for (int k0 = 0; k0 < K; k0 += BK) {
        float4 av = make_float4(0.f, 0.f, 0.f, 0.f);
        if (aBase >= 0)
            av = *reinterpret_cast<const float4*>(A + aBase + k0 + aCol);
        As[aCol + 0][aRow] = av.x;
        As[aCol + 1][aRow] = av.y;
        As[aCol + 2][aRow] = av.z;
        As[aCol + 3][aRow] = av.w;

        float4 bv = *reinterpret_cast<const float4*>(
            Bm + (long)(k0 + bRow) * N + colBase + bCol);
        *reinterpret_cast<float4*>(&Bs[bRow][bCol]) = bv;
        __syncthreads();

#pragma unroll
        for (int kk = 0; kk < BK; kk++) {
            float af[TM], bf[TN];
#pragma unroll
            for (int i = 0; i < TM; i++) af[i] = As[kk][ty * TM + i];
#pragma unroll
            for (int j = 0; j < TN; j++) bf[j] = Bs[kk][tx * TN + j];
#pragma unroll
            for (int i = 0; i < TM; i++)
#pragma unroll
                for (int j = 0; j < TN; j++)
                    acc[i][j] = fmaf(af[i], bf[j], acc[i][j]);
        }
        __syncthreads();
    }

#pragma unroll
    for (int i = 0; i < TM; i++) {
        int row = rowBase + ty * TM + i;
        if (row >= M) continue;
        const float* pr = perRow ? (perRow + (long)(row >> 5) * N) : nullptr;
#pragma unroll
        for (int j = 0; j < TN; j++) {
            int col = colBase + tx * TN + j;
            float c = acc[i][j];
            if (bias) c += bias[col];
            if (pr)   c += pr[col];
            C[(long)row * N + col] = c;
        }
    }
}

// ---------------- logits (h2 @ W3 + b3) + per-slot loss stats ----------------
// one warp per slot row; 8 rows per block; 256 blocks
__global__ __launch_bounds__(256)
void k_loss(const float* __restrict__ W3, const float* __restrict__ b3,
            const float* __restrict__ labels)
{
    const int warpId = threadIdx.x >> 5;
    const int lane   = threadIdx.x & 31;
    const int r = blockIdx.x * 8 + warpId;       // 0..2047
    const float* h2row = g_h2 + (long)r * (FH_ / 2);
    const bool active = (lane < L_);

    float acc = 0.f;
#pragma unroll 4
    for (int kb = 0; kb < (FH_ / 2) / 32; kb++) {
        float v = h2row[kb * 32 + lane];
#pragma unroll
        for (int j = 0; j < 32; j++) {
            float a = __shfl_sync(0xffffffffu, v, j);
            float w = active ? W3[(kb * 32 + j) * L_ + lane] : 0.f;
            acc = fmaf(a, w, acc);
        }
    }
    float x = acc + (active ? b3[lane] : 0.f);
    float y = active ? labels[(long)r * L_ + lane] : -1.0f;

    unsigned ball_bin  = __ballot_sync(0xffffffffu, active && (x > 0.f));
    unsigned ball_one  = __ballot_sync(0xffffffffu, active && (y > 0.5f));
    unsigned ball_real = __ballot_sync(0xffffffffu, active && (y != -1.0f));

    // stable softplus(x) - x*y
    float sp  = fmaxf(x, 0.f) + log1pf(expf(-fabsf(x)));
    float bce = active ? (sp - x * y) : 0.f;
#pragma unroll
    for (int o = 16; o; o >>= 1) bce += __shfl_xor_sync(0xffffffffu, bce, o);

    __shared__ float sm[8][5];
    if (lane == 0) {
        float mf = (ball_real != 0u) ? 1.f : 0.f;
        int co = __popc(ball_bin);
        int cl = __popc(ball_one);
        float cd = (float)(co - cl);
        bool eq = (mf != 0.f) && (co == 1) && (cl == 1);
        float pd = eq ? (float)(__ffs(ball_bin) - __ffs(ball_one)) : 0.f;
        sm[warpId][0] = mf * bce;          // masked bce sum
        sm[warpId][1] = mf;                // mask count
        sm[warpId][2] = mf * cd * cd;      // count sq
        sm[warpId][3] = pd * pd;           // pos sq (0 unless eq)
        sm[warpId][4] = eq ? 1.f : 0.f;    // n_eq
    }
    __syncthreads();
    if (threadIdx.x < 5) {
        float s = 0.f;
        for (int w = 0; w < 8; w++) s += sm[w][threadIdx.x];   // fixed order
        g_part[blockIdx.x * 5 + threadIdx.x] = s;
    }
}

// ---------------- deterministic final reduce ----------------
__global__ __launch_bounds__(256)
void k_final(float* __restrict__ out, int out_size)
{
    __shared__ float sm[256][5];
    int t = threadIdx.x;
    for (int c = 0; c < 5; c++) sm[t][c] = g_part[t * 5 + c];
    __syncthreads();
    for (int s = 128; s > 0; s >>= 1) {
        if (t < s)
            for (int c = 0; c < 5; c++) sm[t][c] += sm[t + s][c];
        __syncthreads();
    }
    if (t == 0) {
        float bce_sum = sm[0][0];
        float mf_sum  = sm[0][1];
        float csq     = sm[0][2];
        float psq     = sm[0][3];
        float neq     = sm[0][4];
        float bce_loss   = bce_sum / (mf_sum * (float)L_);
        float count_loss = csq / (float)MROWS;           // mean over B*P
        float pos_loss   = (neq > 0.f) ? (psq / neq) : 0.f;
        float loss = bce_loss + 10.f * count_loss + 5.f * pos_loss;
        for (int i = 0; i < out_size; i++) out[i] = loss;
    }
}

// ---------------- launch ----------------
extern "C" void kernel_launch(void* const* d_in, const int* in_sizes, int n_in,
                              void* d_out, int out_size)
{
    const float* te   = (const float*)d_in[0];   // [64,512,768]
    const float* pool = (const float*)d_in[1];   // [64,768]
    const int*   pos  = (const int*)  d_in[2];   // [64,32]
    const float* lab  = (const float*)d_in[3];   // [64,960]
    const float* W1   = (const float*)d_in[4];   // [1536,1024]
    const float* b1   = (const float*)d_in[5];   // [1024]
    const float* W2   = (const float*)d_in[6];   // [1024,512]
    const float* b2   = (const float*)d_in[7];   // [512]
    const float* W3   = (const float*)d_in[8];   // [512,30]
    const float* b3   = (const float*)d_in[9];   // [30]

    float *pp, *h1, *h2;
    int   *rowoff;
    cudaGetSymbolAddress((void**)&pp,     g_pp);
    cudaGetSymbolAddress((void**)&h1,     g_h1);
    cudaGetSymbolAddress((void**)&h2,     g_h2);
    cudaGetSymbolAddress((void**)&rowoff, g_rowoff);

    // 1) gather offsets
    k_rowoff<<<(MROWS + 255) / 256, 256>>>(pos);

    // 2) pp[64,1024] = pooler @ W1[768:,:] + b1
    {
        dim3 grid(FH_ / 128, 1);
        sgemm128<<<grid, 256>>>(pool, nullptr, W1 + H_ * FH_, pp,
                                B_, FH_, H_, b1, nullptr);
    }
    // 3) h1[2048,1024] = gather(te) @ W1[:768,:] + pp[b]
    {
        dim3 grid(FH_ / 128, MROWS / 128);
        sgemm128<<<grid, 256>>>(te, rowoff, W1, h1,
                                MROWS, FH_, H_, nullptr, pp);
    }
    // 4) h2[2048,512] = h1 @ W2 + b2
    {
        dim3 grid((FH_ / 2) / 128, MROWS / 128);
        sgemm128<<<grid, 256>>>(h1, nullptr, W2, h2,
                                MROWS, FH_ / 2, FH_, b2, nullptr);
    }
    // 5) logits + per-slot loss stats (one warp per slot)
    k_loss<<<MROWS / 8, 256>>>(W3, b3, lab);

    // 6) deterministic final reduction -> scalar
    k_final<<<1, 256>>>((float*)d_out, out_size);
}

// round 3
// speedup vs baseline: 2.3039x; 2.3039x over previous
#include <cuda_runtime.h>
#include <math.h>
#include <stdint.h>

#define B_   64
#define S_   512
#define P_   32
#define L_   30
#define H_   768
#define FH_  1024
#define MROWS (B_*P_)   // 2048

// ======================= device scratch (no allocation) =======================
__device__ float g_W1T[FH_ * H_];          // W1[:768]^T   [1024,768]
__device__ float g_W2T[(FH_/2) * FH_];     // W2^T         [512,1024]
__device__ float g_h1[MROWS * FH_];        // [2048,1024]
__device__ float g_h2[MROWS * (FH_/2)];    // [2048,512]
__device__ float g_pp[B_ * FH_];           // pooler@W1[768:]+b1
__device__ int   g_rowoff[MROWS];
__device__ float g_part[256 * 5];

// ======================= helpers =======================
__device__ __forceinline__ uint32_t smem_u32(const void* p) {
    uint32_t a;
    asm("{ .reg .u64 t; cvta.to.shared.u64 t, %1; cvt.u32.u64 %0, t; }"
        : "=r"(a) : "l"(p));
    return a;
}
#define CP16(dst_u32, src_ptr) \
    asm volatile("cp.async.cg.shared.global [%0], [%1], 16;" \
        :: "r"(dst_u32), "l"(src_ptr))
#define CP_COMMIT() asm volatile("cp.async.commit_group;")
#define CP_WAIT1()  asm volatile("cp.async.wait_group 1;")
#define CP_WAIT0()  asm volatile("cp.async.wait_group 0;")

__device__ __forceinline__ void tf32split(float v, uint32_t& hi, uint32_t& lo) {
    uint32_t h;
    asm("cvt.rna.tf32.f32 %0, %1;" : "=r"(h) : "f"(v));
    float r = v - __uint_as_float(h);
    uint32_t l;
    asm("cvt.rna.tf32.f32 %0, %1;" : "=r"(l) : "f"(r));
    hi = h; lo = l;
}

__device__ __forceinline__ void mma_tf32(float* d, const uint32_t* a, const uint32_t* b) {
    asm volatile(
        "mma.sync.aligned.m16n8k8.row.col.f32.tf32.tf32.f32 "
        "{%0,%1,%2,%3}, {%4,%5,%6,%7}, {%8,%9}, {%0,%1,%2,%3};"
        : "+f"(d[0]), "+f"(d[1]), "+f"(d[2]), "+f"(d[3])
        : "r"(a[0]), "r"(a[1]), "r"(a[2]), "r"(a[3]), "r"(b[0]), "r"(b[1]));
}

// ======================= pre-pass kernels =======================
__global__ void k_rowoff(const int* __restrict__ pos) {
    int r = blockIdx.x * blockDim.x + threadIdx.x;
    if (r < MROWS) g_rowoff[r] = ((r >> 5) * S_ + pos[r]) * H_;
}

// transpose src[KK,NN] -> dst[NN,KK]
template<int KK, int NN>
__global__ __launch_bounds__(256) void k_T(const float* __restrict__ src,
                                           float* __restrict__ dst) {
    __shared__ float t[32][33];
    int n0 = blockIdx.x * 32, k0 = blockIdx.y * 32;
    int tx = threadIdx.x, ty = threadIdx.y;
#pragma unroll
    for (int j = 0; j < 4; j++)
        t[ty + 8 * j][tx] = src[(size_t)(k0 + ty + 8 * j) * NN + n0 + tx];
    __syncthreads();
#pragma unroll
    for (int j = 0; j < 4; j++)
        dst[(size_t)(n0 + ty + 8 * j) * KK + k0 + tx] = t[tx][ty + 8 * j];
}

// pp[64,1024] = pooler @ W1[768:1536] + b1
__global__ __launch_bounds__(128) void k_pp(const float* __restrict__ pooler,
                                            const float* __restrict__ W1,
                                            const float* __restrict__ b1) {
    __shared__ float a[8][H_];
    int bg = blockIdx.y;
    int col = blockIdx.x * 128 + threadIdx.x;
    for (int i = threadIdx.x; i < 8 * H_; i += 128) {
        int rr = i / H_, cc = i % H_;
        a[rr][cc] = pooler[(size_t)(bg * 8 + rr) * H_ + cc];
    }
    __syncthreads();
    const float* wp = W1 + (size_t)H_ * FH_ + col;
    float acc[8];
#pragma unroll
    for (int j = 0; j < 8; j++) acc[j] = 0.f;
#pragma unroll 4
    for (int k = 0; k < H_; k++) {
        float w = wp[(size_t)k * FH_];
#pragma unroll
        for (int j = 0; j < 8; j++) acc[j] = fmaf(a[j][k], w, acc[j]);
    }
    float bb = b1[col];
#pragma unroll
    for (int j = 0; j < 8; j++)
        g_pp[(size_t)(bg * 8 + j) * FH_ + col] = acc[j] + bb;
}

// ======================= tf32x3 mma.sync GEMM =======================
// MODE 0: h1[2048,1024] = gather(te) @ W1T^T + pp[b]    (BM=128,BN=128,K=768)
// MODE 1: h2[2048, 512] = h1 @ W2T^T + b2               (BM=128,BN=64, K=1024)
template<int MODE>
__global__ __launch_bounds__(256) void mma_gemm(
    const float* __restrict__ Asrc, const int* __restrict__ rowoff,
    const float* __restrict__ Bsrc, float* __restrict__ Cout,
    const float* __restrict__ addv)
{
    constexpr int BM  = 128;
    constexpr int BN  = (MODE == 0) ? 128 : 64;
    constexpr int K   = (MODE == 0) ? H_ : FH_;
    constexpr int NIT = K / 32;
    constexpr int LDO = (MODE == 0) ? FH_ : (FH_ / 2);
    constexpr int MT  = (MODE == 0) ? 2 : 1;
    constexpr int BCH = BN * 8 / 256;          // B chunks per thread (4 or 2)
    constexpr int ABUF = 128 * 36;             // floats per A buffer
    constexpr int BBUF = BN * 36;              // floats per B buffer

    extern __shared__ float sm[];
    float* AsB = sm;                  // [2][ABUF]
    float* BsB = sm + 2 * ABUF;       // [2][BBUF]

    const int tid = threadIdx.x, wid = tid >> 5, lane = tid & 31;
    const int rowBase = blockIdx.y * BM, colBase = blockIdx.x * BN;
    const int warpRow = (MODE == 0) ? (wid & 3) * 32 : wid * 16;
    const int warpCol = (MODE == 0) ? (wid >> 2) * 64 : 0;

    // staging pointers
    const float* aptr[4];
    int arow[4];
#pragma unroll
    for (int j = 0; j < 4; j++) {
        int r = (tid >> 3) + j * 32;
        arow[j] = r;
        if (MODE == 0) aptr[j] = Asrc + rowoff[rowBase + r];
        else           aptr[j] = Asrc + (size_t)(rowBase + r) * K;
    }
    const float* bptr[4];
    int brow[4];
#pragma unroll
    for (int j = 0; j < BCH; j++) {
        int n = (tid >> 3) + j * 32;
        brow[j] = n;
        bptr[j] = Bsrc + (size_t)(colBase + n) * K;
    }
    const int acol = (tid & 7) * 4;
    const uint32_t smA = smem_u32(AsB), smB = smem_u32(BsB);

    float acc[MT][8][4];
#pragma unroll
    for (int mt = 0; mt < MT; mt++)
#pragma unroll
        for (int nt = 0; nt < 8; nt++)
#pragma unroll
            for (int e = 0; e < 4; e++) acc[mt][nt][e] = 0.f;

#define STAGE(buf, k0) do { \
    uint32_t sa = smA + (buf) * (ABUF * 4); \
    _Pragma("unroll") \
    for (int j = 0; j < 4; j++) \
        CP16(sa + (uint32_t)(arow[j] * 36 + acol) * 4, aptr[j] + (k0) + acol); \
    uint32_t sbp = smB + (buf) * (BBUF * 4); \
    _Pragma("unroll") \
    for (int j = 0; j < BCH; j++) \
        CP16(sbp + (uint32_t)(brow[j] * 36 + acol) * 4, bptr[j] + (k0) + acol); \
    CP_COMMIT(); \
} while (0)

    STAGE(0, 0);
    for (int it = 0; it < NIT; ++it) {
        if (it + 1 < NIT) { STAGE((it + 1) & 1, (it + 1) * 32); CP_WAIT1(); }
        else              { CP_WAIT0(); }
        __syncthreads();
        const float* As = AsB + (it & 1) * ABUF;
        const float* Bs = BsB + (it & 1) * BBUF;
#pragma unroll
        for (int ks = 0; ks < 4; ks++) {
            uint32_t af[MT][4][2];
#pragma unroll
            for (int mt = 0; mt < MT; mt++) {
                int r0 = warpRow + mt * 16 + (lane >> 2);
                int c  = ks * 8 + (lane & 3);
                tf32split(As[r0 * 36 + c],           af[mt][0][0], af[mt][0][1]);
                tf32split(As[(r0 + 8) * 36 + c],     af[mt][1][0], af[mt][1][1]);
                tf32split(As[r0 * 36 + c + 4],       af[mt][2][0], af[mt][2][1]);
                tf32split(As[(r0 + 8) * 36 + c + 4], af[mt][3][0], af[mt][3][1]);
            }
#pragma unroll
            for (int nt = 0; nt < 8; nt++) {
                int n0 = warpCol + nt * 8 + (lane >> 2);
                int c  = ks * 8 + (lane & 3);
                uint32_t b0h, b0l, b1h, b1l;
                tf32split(Bs[n0 * 36 + c],     b0h, b0l);
                tf32split(Bs[n0 * 36 + c + 4], b1h, b1l);
                uint32_t bh[2] = { b0h, b1h };
                uint32_t bl[2] = { b0l, b1l };
#pragma unroll
                for (int mt = 0; mt < MT; mt++) {
                    uint32_t ah[4] = { af[mt][0][0], af[mt][1][0], af[mt][2][0], af[mt][3][0] };
                    uint32_t al[4] = { af[mt][0][1], af[mt][1][1], af[mt][2][1], af[mt][3][1] };
                    mma_tf32(acc[mt][nt], ah, bh);   // a0*b0
                    mma_tf32(acc[mt][nt], al, bh);   // a1*b0
                    mma_tf32(acc[mt][nt], ah, bl);   // a0*b1
                }
            }
        }
        __syncthreads();
    }
#undef STAGE

    // epilogue: D frag -> global (+ pp or bias)
#pragma unroll
    for (int mt = 0; mt < MT; mt++) {
#pragma unroll
        for (int nt = 0; nt < 8; nt++) {
            int r0 = rowBase + warpRow + mt * 16 + (lane >> 2);
            int c  = colBase + warpCol + nt * 8 + (lane & 3) * 2;
            float2 v0 = make_float2(acc[mt][nt][0], acc[mt][nt][1]);
            float2 v1 = make_float2(acc[mt][nt][2], acc[mt][nt][3]);
            if (MODE == 0) {
                float2 p0 = *(const float2*)&addv[(size_t)(r0 >> 5) * FH_ + c];
                float2 p1 = *(const float2*)&addv[(size_t)((r0 + 8) >> 5) * FH_ + c];
                v0.x += p0.x; v0.y += p0.y; v1.x += p1.x; v1.y += p1.y;
            } else {
                float2 bb = *(const float2*)&addv[c];
                v0.x += bb.x; v0.y += bb.y; v1.x += bb.x; v1.y += bb.y;
            }
            *(float2*)&Cout[(size_t)r0 * LDO + c]       = v0;
            *(float2*)&Cout[(size_t)(r0 + 8) * LDO + c] = v1;
        }
    }
}

// ======================= loss kernels =======================
__global__ __launch_bounds__(256)
void k_loss(const float* __restrict__ W3, const float* __restrict__ b3,
            const float* __restrict__ labels)
{
    const int warpId = threadIdx.x >> 5;
    const int lane   = threadIdx.x & 31;
    const int r = blockIdx.x * 8 + warpId;
    const float* h2row = g_h2 + (size_t)r * (FH_ / 2);
    const bool active = (lane < L_);

    float acc = 0.f;
#pragma unroll 4
    for (int kb = 0; kb < (FH_ / 2) / 32; kb++) {
        float v = h2row[kb * 32 + lane];
#pragma unroll
        for (int j = 0; j < 32; j++) {
            float a = __shfl_sync(0xffffffffu, v, j);
            float w = active ? W3[(kb * 32 + j) * L_ + lane] : 0.f;
            acc = fmaf(a, w, acc);
        }
    }
    float x = acc + (active ? b3[lane] : 0.f);
    float y = active ? labels[(size_t)r * L_ + lane] : -1.0f;

    unsigned ball_bin  = __ballot_sync(0xffffffffu, active && (x > 0.f));
    unsigned ball_one  = __ballot_sync(0xffffffffu, active && (y > 0.5f));
    unsigned ball_real = __ballot_sync(0xffffffffu, active && (y != -1.0f));

    float sp  = fmaxf(x, 0.f) + log1pf(expf(-fabsf(x)));
    float bce = active ? (sp - x * y) : 0.f;
#pragma unroll
    for (int o = 16; o; o >>= 1) bce += __shfl_xor_sync(0xffffffffu, bce, o);

    __shared__ float sml[8][5];
    if (lane == 0) {
        float mf = (ball_real != 0u) ? 1.f : 0.f;
        int co = __popc(ball_bin);
        int cl = __popc(ball_one);
        float cd = (float)(co - cl);
        bool eq = (mf != 0.f) && (co == 1) && (cl == 1);
        float pd = eq ? (float)(__ffs(ball_bin) - __ffs(ball_one)) : 0.f;
        sml[warpId][0] = mf * bce;
        sml[warpId][1] = mf;
        sml[warpId][2] = mf * cd * cd;
        sml[warpId][3] = pd * pd;
        sml[warpId][4] = eq ? 1.f : 0.f;
    }
    __syncthreads();
    if (threadIdx.x < 5) {
        float s = 0.f;
        for (int w = 0; w < 8; w++) s += sml[w][threadIdx.x];
        g_part[blockIdx.x * 5 + threadIdx.x] = s;
    }
}

__global__ __launch_bounds__(256)
void k_final(float* __restrict__ out, int out_size)
{
    __shared__ float smf[256][5];
    int t = threadIdx.x;
    for (int c = 0; c < 5; c++) smf[t][c] = g_part[t * 5 + c];
    __syncthreads();
    for (int s = 128; s > 0; s >>= 1) {
        if (t < s)
            for (int c = 0; c < 5; c++) smf[t][c] += smf[t + s][c];
        __syncthreads();
    }
    if (t == 0) {
        float bce_loss   = smf[0][0] / (smf[0][1] * (float)L_);
        float count_loss = smf[0][2] / (float)MROWS;
        float pos_loss   = (smf[0][4] > 0.f) ? (smf[0][3] / smf[0][4]) : 0.f;
        float loss = bce_loss + 10.f * count_loss + 5.f * pos_loss;
        for (int i = 0; i < out_size; i++) out[i] = loss;
    }
}

// ======================= launch =======================
extern "C" void kernel_launch(void* const* d_in, const int* in_sizes, int n_in,
                              void* d_out, int out_size)
{
    const float* te   = (const float*)d_in[0];
    const float* pool = (const float*)d_in[1];
    const int*   pos  = (const int*)  d_in[2];
    const float* lab  = (const float*)d_in[3];
    const float* W1   = (const float*)d_in[4];
    const float* b1   = (const float*)d_in[5];
    const float* W2   = (const float*)d_in[6];
    const float* b2   = (const float*)d_in[7];
    const float* W3   = (const float*)d_in[8];
    const float* b3   = (const float*)d_in[9];

    float *w1t, *w2t, *h1, *h2, *pp;
    int* rowoff;
    cudaGetSymbolAddress((void**)&w1t,    g_W1T);
    cudaGetSymbolAddress((void**)&w2t,    g_W2T);
    cudaGetSymbolAddress((void**)&h1,     g_h1);
    cudaGetSymbolAddress((void**)&h2,     g_h2);
    cudaGetSymbolAddress((void**)&pp,     g_pp);
    cudaGetSymbolAddress((void**)&rowoff, g_rowoff);

    const int SM0 = (2 * 128 * 36 + 2 * 128 * 36) * 4;   // 73728
    const int SM1 = (2 * 128 * 36 + 2 * 64 * 36) * 4;    // 55296
    cudaFuncSetAttribute(mma_gemm<0>, cudaFuncAttributeMaxDynamicSharedMemorySize, SM0);
    cudaFuncSetAttribute(mma_gemm<1>, cudaFuncAttributeMaxDynamicSharedMemorySize, SM1);

    // pre-passes
    k_rowoff<<<(MROWS + 255) / 256, 256>>>(pos);
    k_T<H_, FH_><<<dim3(FH_ / 32, H_ / 32), dim3(32, 8)>>>(W1, w1t);
    k_T<FH_, FH_ / 2><<<dim3((FH_ / 2) / 32, FH_ / 32), dim3(32, 8)>>>(W2, w2t);
    k_pp<<<dim3(FH_ / 128, B_ / 8), 128>>>(pool, W1, b1);

    // tensor-core GEMMs (tf32x3 emulated fp32)
    mma_gemm<0><<<dim3(FH_ / 128, MROWS / 128), 256, SM0>>>(te, rowoff, w1t, h1, pp);
    mma_gemm<1><<<dim3((FH_ / 2) / 64, MROWS / 128), 256, SM1>>>(h1, nullptr, w2t, h2, b2);

    // loss + reduce
    k_loss<<<MROWS / 8, 256>>>(W3, b3, lab);
    k_final<<<1, 256>>>((float*)d_out, out_size);
}

// round 4
// speedup vs baseline: 2.6956x; 1.1700x over previous
#include <cuda_runtime.h>
#include <math.h>
#include <stdint.h>

#define B_   64
#define S_   512
#define P_   32
#define L_   30
#define H_   768
#define FH_  1024
#define MROWS (B_*P_)   // 2048
#define KSPLIT 16

// ======================= device scratch (no allocation) =======================
__device__ float g_W1T[FH_ * H_];          // W1[:768]^T   [1024,768]
__device__ float g_W2T[(FH_/2) * FH_];     // W2^T         [512,1024]
__device__ float g_h1[MROWS * FH_];        // [2048,1024]
__device__ float g_h2[MROWS * (FH_/2)];    // [2048,512]
__device__ float g_pp[B_ * FH_];           // pooler@W1[768:]+b1
__device__ float g_ppp[KSPLIT][B_ * FH_];  // split-K partials
__device__ int   g_rowoff[MROWS];
__device__ float g_part[256 * 5];

// ======================= helpers =======================
__device__ __forceinline__ uint32_t smem_u32(const void* p) {
    uint32_t a;
    asm("{ .reg .u64 t; cvta.to.shared.u64 t, %1; cvt.u32.u64 %0, t; }"
        : "=r"(a) : "l"(p));
    return a;
}
#define CP16(dst_u32, src_ptr) \
    asm volatile("cp.async.cg.shared.global [%0], [%1], 16;" \
        :: "r"(dst_u32), "l"(src_ptr))
#define CP_COMMIT() asm volatile("cp.async.commit_group;")
#define CP_WAIT1()  asm volatile("cp.async.wait_group 1;")
#define CP_WAIT0()  asm volatile("cp.async.wait_group 0;")

__device__ __forceinline__ void tf32split(float v, uint32_t& hi, uint32_t& lo) {
    uint32_t h;
    asm("cvt.rna.tf32.f32 %0, %1;" : "=r"(h) : "f"(v));
    float r = v - __uint_as_float(h);
    uint32_t l;
    asm("cvt.rna.tf32.f32 %0, %1;" : "=r"(l) : "f"(r));
    hi = h; lo = l;
}

__device__ __forceinline__ void mma_tf32(float* d, const uint32_t* a, const uint32_t* b) {
    asm volatile(
        "mma.sync.aligned.m16n8k8.row.col.f32.tf32.tf32.f32 "
        "{%0,%1,%2,%3}, {%4,%5,%6,%7}, {%8,%9}, {%0,%1,%2,%3};"
        : "+f"(d[0]), "+f"(d[1]), "+f"(d[2]), "+f"(d[3])
        : "r"(a[0]), "r"(a[1]), "r"(a[2]), "r"(a[3]), "r"(b[0]), "r"(b[1]));
}

// ======================= pre-pass kernels =======================
__global__ void k_rowoff(const int* __restrict__ pos) {
    int r = blockIdx.x * blockDim.x + threadIdx.x;
    if (r < MROWS) g_rowoff[r] = ((r >> 5) * S_ + pos[r]) * H_;
}

// transpose src[KK,NN] -> dst[NN,KK]
template<int KK, int NN>
__global__ __launch_bounds__(256) void k_T(const float* __restrict__ src,
                                           float* __restrict__ dst) {
    __shared__ float t[32][33];
    int n0 = blockIdx.x * 32, k0 = blockIdx.y * 32;
    int tx = threadIdx.x, ty = threadIdx.y;
#pragma unroll
    for (int j = 0; j < 4; j++)
        t[ty + 8 * j][tx] = src[(size_t)(k0 + ty + 8 * j) * NN + n0 + tx];
    __syncthreads();
#pragma unroll
    for (int j = 0; j < 4; j++)
        dst[(size_t)(n0 + ty + 8 * j) * KK + k0 + tx] = t[tx][ty + 8 * j];
}

// ---------- split-K pooler GEMM: partials over K chunks of 48 ----------
// grid (FH/128, KSPLIT), block 256: tx (0..31) -> 4 cols, ty (0..7) -> 8 rows
__global__ __launch_bounds__(256) void k_pp_part(const float* __restrict__ pooler,
                                                 const float* __restrict__ W1) {
    constexpr int KC = H_ / KSPLIT;      // 48
    __shared__ float a[B_][KC + 1];
    const int ks = blockIdx.y, k0 = ks * KC;
    const int colBase = blockIdx.x * 128;
    const int tid = threadIdx.x;
    const int tx = tid & 31, ty = tid >> 5;

    for (int idx = tid; idx < B_ * KC; idx += 256) {
        int row = idx / KC, kk = idx % KC;
        a[row][kk] = pooler[(size_t)row * H_ + k0 + kk];
    }
    __syncthreads();

    const float* wp = W1 + (size_t)H_ * FH_ + (size_t)k0 * FH_ + colBase + tx * 4;
    float acc[8][4];
#pragma unroll
    for (int r = 0; r < 8; r++)
#pragma unroll
        for (int j = 0; j < 4; j++) acc[r][j] = 0.f;

#pragma unroll 4
    for (int kk = 0; kk < KC; kk++) {
        float4 w = *(const float4*)(wp + (size_t)kk * FH_);
#pragma unroll
        for (int r = 0; r < 8; r++) {
            float av = a[ty * 8 + r][kk];
            acc[r][0] = fmaf(av, w.x, acc[r][0]);
            acc[r][1] = fmaf(av, w.y, acc[r][1]);
            acc[r][2] = fmaf(av, w.z, acc[r][2]);
            acc[r][3] = fmaf(av, w.w, acc[r][3]);
        }
    }
#pragma unroll
    for (int r = 0; r < 8; r++)
        *(float4*)&g_ppp[ks][(size_t)(ty * 8 + r) * FH_ + colBase + tx * 4] =
            make_float4(acc[r][0], acc[r][1], acc[r][2], acc[r][3]);
}

// fixed-order reduce of KSPLIT partials + b1 -> g_pp
__global__ __launch_bounds__(256) void k_pp_reduce(const float* __restrict__ b1) {
    int i4 = blockIdx.x * 256 + threadIdx.x;          // float4 index
    int col = (i4 * 4) % FH_;
    float4 s = make_float4(0.f, 0.f, 0.f, 0.f);
#pragma unroll
    for (int ks = 0; ks < KSPLIT; ks++) {
        float4 v = *(const float4*)&g_ppp[ks][(size_t)i4 * 4];
        s.x += v.x; s.y += v.y; s.z += v.z; s.w += v.w;
    }
    float4 bb = *(const float4*)&b1[col];
    s.x += bb.x; s.y += bb.y; s.z += bb.z; s.w += bb.w;
    *(float4*)&g_pp[(size_t)i4 * 4] = s;
}

// ======================= tf32x3 mma.sync GEMM =======================
// MODE 0: h1[2048,1024] = gather(te) @ W1T^T + pp[b]    (BM=128,BN=128,K=768)
// MODE 1: h2[2048, 512] = h1 @ W2T^T + b2               (BM=128,BN=64, K=1024)
template<int MODE>
__global__ __launch_bounds__(256) void mma_gemm(
    const float* __restrict__ Asrc, const int* __restrict__ rowoff,
    const float* __restrict__ Bsrc, float* __restrict__ Cout,
    const float* __restrict__ addv)
{
    constexpr int BM  = 128;
    constexpr int BN  = (MODE == 0) ? 128 : 64;
    constexpr int K   = (MODE == 0) ? H_ : FH_;
    constexpr int NIT = K / 32;
    constexpr int LDO = (MODE == 0) ? FH_ : (FH_ / 2);
    constexpr int MT  = (MODE == 0) ? 2 : 1;
    constexpr int BCH = BN * 8 / 256;          // B chunks per thread (4 or 2)
    constexpr int ABUF = 128 * 36;             // floats per A buffer
    constexpr int BBUF = BN * 36;              // floats per B buffer

    extern __shared__ float sm[];
    float* AsB = sm;                  // [2][ABUF]
    float* BsB = sm + 2 * ABUF;       // [2][BBUF]

    const int tid = threadIdx.x, wid = tid >> 5, lane = tid & 31;
    const int rowBase = blockIdx.y * BM, colBase = blockIdx.x * BN;
    const int warpRow = (MODE == 0) ? (wid & 3) * 32 : wid * 16;
    const int warpCol = (MODE == 0) ? (wid >> 2) * 64 : 0;

    // staging pointers
    const float* aptr[4];
    int arow[4];
#pragma unroll
    for (int j = 0; j < 4; j++) {
        int r = (tid >> 3) + j * 32;
        arow[j] = r;
        if (MODE == 0) aptr[j] = Asrc + rowoff[rowBase + r];
        else           aptr[j] = Asrc + (size_t)(rowBase + r) * K;
    }
    const float* bptr[4];
    int brow[4];
#pragma unroll
    for (int j = 0; j < BCH; j++) {
        int n = (tid >> 3) + j * 32;
        brow[j] = n;
        bptr[j] = Bsrc + (size_t)(colBase + n) * K;
    }
    const int acol = (tid & 7) * 4;
    const uint32_t smA = smem_u32(AsB), smB = smem_u32(BsB);

    float acc[MT][8][4];
#pragma unroll
    for (int mt = 0; mt < MT; mt++)
#pragma unroll
        for (int nt = 0; nt < 8; nt++)
#pragma unroll
            for (int e = 0; e < 4; e++) acc[mt][nt][e] = 0.f;

#define STAGE(buf, k0) do { \
    uint32_t sa = smA + (buf) * (ABUF * 4); \
    _Pragma("unroll") \
    for (int j = 0; j < 4; j++) \
        CP16(sa + (uint32_t)(arow[j] * 36 + acol) * 4, aptr[j] + (k0) + acol); \
    uint32_t sbp = smB + (buf) * (BBUF * 4); \
    _Pragma("unroll") \
    for (int j = 0; j < BCH; j++) \
        CP16(sbp + (uint32_t)(brow[j] * 36 + acol) * 4, bptr[j] + (k0) + acol); \
    CP_COMMIT(); \
} while (0)

    STAGE(0, 0);
    for (int it = 0; it < NIT; ++it) {
        if (it + 1 < NIT) { STAGE((it + 1) & 1, (it + 1) * 32); CP_WAIT1(); }
        else              { CP_WAIT0(); }
        __syncthreads();
        const float* As = AsB + (it & 1) * ABUF;
        const float* Bs = BsB + (it & 1) * BBUF;
#pragma unroll
        for (int ks = 0; ks < 4; ks++) {
            uint32_t af[MT][4][2];
#pragma unroll
            for (int mt = 0; mt < MT; mt++) {
                int r0 = warpRow + mt * 16 + (lane >> 2);
                int c  = ks * 8 + (lane & 3);
                tf32split(As[r0 * 36 + c],           af[mt][0][0], af[mt][0][1]);
                tf32split(As[(r0 + 8) * 36 + c],     af[mt][1][0], af[mt][1][1]);
                tf32split(As[r0 * 36 + c + 4],       af[mt][2][0], af[mt][2][1]);
                tf32split(As[(r0 + 8) * 36 + c + 4], af[mt][3][0], af[mt][3][1]);
            }
#pragma unroll
            for (int nt = 0; nt < 8; nt++) {
                int n0 = warpCol + nt * 8 + (lane >> 2);
                int c  = ks * 8 + (lane & 3);
                uint32_t b0h, b0l, b1h, b1l;
                tf32split(Bs[n0 * 36 + c],     b0h, b0l);
                tf32split(Bs[n0 * 36 + c + 4], b1h, b1l);
                uint32_t bh[2] = { b0h, b1h };
                uint32_t bl[2] = { b0l, b1l };
#pragma unroll
                for (int mt = 0; mt < MT; mt++) {
                    uint32_t ah[4] = { af[mt][0][0], af[mt][1][0], af[mt][2][0], af[mt][3][0] };
                    uint32_t al[4] = { af[mt][0][1], af[mt][1][1], af[mt][2][1], af[mt][3][1] };
                    mma_tf32(acc[mt][nt], ah, bh);   // a0*b0
                    mma_tf32(acc[mt][nt], al, bh);   // a1*b0
                    mma_tf32(acc[mt][nt], ah, bl);   // a0*b1
                }
            }
        }
        __syncthreads();
    }
#undef STAGE

    // epilogue: D frag -> global (+ pp or bias)
#pragma unroll
    for (int mt = 0; mt < MT; mt++) {
#pragma unroll
        for (int nt = 0; nt < 8; nt++) {
            int r0 = rowBase + warpRow + mt * 16 + (lane >> 2);
            int c  = colBase + warpCol + nt * 8 + (lane & 3) * 2;
            float2 v0 = make_float2(acc[mt][nt][0], acc[mt][nt][1]);
            float2 v1 = make_float2(acc[mt][nt][2], acc[mt][nt][3]);
            if (MODE == 0) {
                float2 p0 = *(const float2*)&addv[(size_t)(r0 >> 5) * FH_ + c];
                float2 p1 = *(const float2*)&addv[(size_t)((r0 + 8) >> 5) * FH_ + c];
                v0.x += p0.x; v0.y += p0.y; v1.x += p1.x; v1.y += p1.y;
            } else {
                float2 bb = *(const float2*)&addv[c];
                v0.x += bb.x; v0.y += bb.y; v1.x += bb.x; v1.y += bb.y;
            }
            *(float2*)&Cout[(size_t)r0 * LDO + c]       = v0;
            *(float2*)&Cout[(size_t)(r0 + 8) * LDO + c] = v1;
        }
    }
}

// ======================= loss kernels =======================
__global__ __launch_bounds__(256)
void k_loss(const float* __restrict__ W3, const float* __restrict__ b3,
            const float* __restrict__ labels)
{
    const int warpId = threadIdx.x >> 5;
    const int lane   = threadIdx.x & 31;
    const int r = blockIdx.x * 8 + warpId;
    const float* h2row = g_h2 + (size_t)r * (FH_ / 2);
    const bool active = (lane < L_);

    float acc = 0.f;
#pragma unroll 4
    for (int kb = 0; kb < (FH_ / 2) / 32; kb++) {
        float v = h2row[kb * 32 + lane];
#pragma unroll
        for (int j = 0; j < 32; j++) {
            float a = __shfl_sync(0xffffffffu, v, j);
            float w = active ? W3[(kb * 32 + j) * L_ + lane] : 0.f;
            acc = fmaf(a, w, acc);
        }
    }
    float x = acc + (active ? b3[lane] : 0.f);
    float y = active ? labels[(size_t)r * L_ + lane] : -1.0f;

    unsigned ball_bin  = __ballot_sync(0xffffffffu, active && (x > 0.f));
    unsigned ball_one  = __ballot_sync(0xffffffffu, active && (y > 0.5f));
    unsigned ball_real = __ballot_sync(0xffffffffu, active && (y != -1.0f));

    float sp  = fmaxf(x, 0.f) + log1pf(expf(-fabsf(x)));
    float bce = active ? (sp - x * y) : 0.f;
#pragma unroll
    for (int o = 16; o; o >>= 1) bce += __shfl_xor_sync(0xffffffffu, bce, o);

    __shared__ float sml[8][5];
    if (lane == 0) {
        float mf = (ball_real != 0u) ? 1.f : 0.f;
        int co = __popc(ball_bin);
        int cl = __popc(ball_one);
        float cd = (float)(co - cl);
        bool eq = (mf != 0.f) && (co == 1) && (cl == 1);
        float pd = eq ? (float)(__ffs(ball_bin) - __ffs(ball_one)) : 0.f;
        sml[warpId][0] = mf * bce;
        sml[warpId][1] = mf;
        sml[warpId][2] = mf * cd * cd;
        sml[warpId][3] = pd * pd;
        sml[warpId][4] = eq ? 1.f : 0.f;
    }
    __syncthreads();
    if (threadIdx.x < 5) {
        float s = 0.f;
        for (int w = 0; w < 8; w++) s += sml[w][threadIdx.x];
        g_part[blockIdx.x * 5 + threadIdx.x] = s;
    }
}

__global__ __launch_bounds__(256)
void k_final(float* __restrict__ out, int out_size)
{
    __shared__ float smf[256][5];
    int t = threadIdx.x;
    for (int c = 0; c < 5; c++) smf[t][c] = g_part[t * 5 + c];
    __syncthreads();
    for (int s = 128; s > 0; s >>= 1) {
        if (t < s)
            for (int c = 0; c < 5; c++) smf[t][c] += smf[t + s][c];
        __syncthreads();
    }
    if (t == 0) {
        float bce_loss   = smf[0][0] / (smf[0][1] * (float)L_);
        float count_loss = smf[0][2] / (float)MROWS;
        float pos_loss   = (smf[0][4] > 0.f) ? (smf[0][3] / smf[0][4]) : 0.f;
        float loss = bce_loss + 10.f * count_loss + 5.f * pos_loss;
        for (int i = 0; i < out_size; i++) out[i] = loss;
    }
}

// ======================= launch =======================
extern "C" void kernel_launch(void* const* d_in, const int* in_sizes, int n_in,
                              void* d_out, int out_size)
{
    const float* te   = (const float*)d_in[0];
    const float* pool = (const float*)d_in[1];
    const int*   pos  = (const int*)  d_in[2];
    const float* lab  = (const float*)d_in[3];
    const float* W1   = (const float*)d_in[4];
    const float* b1   = (const float*)d_in[5];
    const float* W2   = (const float*)d_in[6];
    const float* b2   = (const float*)d_in[7];
    const float* W3   = (const float*)d_in[8];
    const float* b3   = (const float*)d_in[9];

    float *w1t, *w2t, *h1, *h2, *pp;
    int* rowoff;
    cudaGetSymbolAddress((void**)&w1t,    g_W1T);
    cudaGetSymbolAddress((void**)&w2t,    g_W2T);
    cudaGetSymbolAddress((void**)&h1,     g_h1);
    cudaGetSymbolAddress((void**)&h2,     g_h2);
    cudaGetSymbolAddress((void**)&pp,     g_pp);
    cudaGetSymbolAddress((void**)&rowoff, g_rowoff);

    const int SM0 = (2 * 128 * 36 + 2 * 128 * 36) * 4;   // 73728
    const int SM1 = (2 * 128 * 36 + 2 * 64 * 36) * 4;    // 55296
    cudaFuncSetAttribute(mma_gemm<0>, cudaFuncAttributeMaxDynamicSharedMemorySize, SM0);
    cudaFuncSetAttribute(mma_gemm<1>, cudaFuncAttributeMaxDynamicSharedMemorySize, SM1);

    // pre-passes
    k_rowoff<<<(MROWS + 255) / 256, 256>>>(pos);
    k_T<H_, FH_><<<dim3(FH_ / 32, H_ / 32), dim3(32, 8)>>>(W1, w1t);
    k_T<FH_, FH_ / 2><<<dim3((FH_ / 2) / 32, FH_ / 32), dim3(32, 8)>>>(W2, w2t);
    k_pp_part<<<dim3(FH_ / 128, KSPLIT), 256>>>(pool, W1);
    k_pp_reduce<<<(B_ * FH_ / 4) / 256, 256>>>(b1);

    // tensor-core GEMMs (tf32x3 emulated fp32)
    mma_gemm<0><<<dim3(FH_ / 128, MROWS / 128), 256, SM0>>>(te, rowoff, w1t, h1, pp);
    mma_gemm<1><<<dim3((FH_ / 2) / 64, MROWS / 128), 256, SM1>>>(h1, nullptr, w2t, h2, b2);

    // loss + reduce
    k_loss<<<MROWS / 8, 256>>>(W3, b3, lab);
    k_final<<<1, 256>>>((float*)d_out, out_size);
}

// round 5
// speedup vs baseline: 2.8446x; 1.0553x over previous
#include <cuda_runtime.h>
#include <math.h>
#include <stdint.h>

#define B_   64
#define S_   512
#define P_   32
#define L_   30
#define H_   768
#define FH_  1024
#define MROWS (B_*P_)   // 2048
#define KSPLIT 32

// ======================= device scratch (no allocation) =======================
__device__ float g_W1Ts[FH_ * H_ * 2];       // W1[:768]^T split (hi,lo) interleaved
__device__ float g_W2Ts[(FH_/2) * FH_ * 2];  // W2^T split (hi,lo) interleaved
__device__ float g_h1[MROWS * FH_];          // [2048,1024] fp32
__device__ float g_h2[MROWS * (FH_/2)];      // [2048,512]
__device__ float g_pp[B_ * FH_];             // pooler@W1[768:]+b1
__device__ float g_ppp[KSPLIT][B_ * FH_];    // split-K partials
__device__ int   g_rowoff[MROWS];
__device__ float g_part[256 * 5];

// ======================= helpers =======================
__device__ __forceinline__ uint32_t smem_u32(const void* p) {
    uint32_t a;
    asm("{ .reg .u64 t; cvta.to.shared.u64 t, %1; cvt.u32.u64 %0, t; }"
        : "=r"(a) : "l"(p));
    return a;
}
#define CP16(dst_u32, src_ptr) \
    asm volatile("cp.async.cg.shared.global [%0], [%1], 16;" \
        :: "r"(dst_u32), "l"(src_ptr))
#define CP_COMMIT() asm volatile("cp.async.commit_group;")
#define CP_WAIT1()  asm volatile("cp.async.wait_group 1;")
#define CP_WAIT0()  asm volatile("cp.async.wait_group 0;")

__device__ __forceinline__ void tf32split(float v, uint32_t& hi, uint32_t& lo) {
    uint32_t h;
    asm("cvt.rna.tf32.f32 %0, %1;" : "=r"(h) : "f"(v));
    float r = v - __uint_as_float(h);
    uint32_t l;
    asm("cvt.rna.tf32.f32 %0, %1;" : "=r"(l) : "f"(r));
    hi = h; lo = l;
}

__device__ __forceinline__ void mma_tf32(float* d, const uint32_t* a, const uint32_t* b) {
    asm volatile(
        "mma.sync.aligned.m16n8k8.row.col.f32.tf32.tf32.f32 "
        "{%0,%1,%2,%3}, {%4,%5,%6,%7}, {%8,%9}, {%0,%1,%2,%3};"
        : "+f"(d[0]), "+f"(d[1]), "+f"(d[2]), "+f"(d[3])
        : "r"(a[0]), "r"(a[1]), "r"(a[2]), "r"(a[3]), "r"(b[0]), "r"(b[1]));
}

// ======================= pre-pass kernels =======================
__global__ void k_rowoff(const int* __restrict__ pos) {
    int r = blockIdx.x * blockDim.x + threadIdx.x;
    if (r < MROWS) g_rowoff[r] = ((r >> 5) * S_ + pos[r]) * H_;
}

// transpose + tf32-split: src[KK,NN] -> dst float2 (hi,lo) at [NN,KK]
template<int KK, int NN>
__global__ __launch_bounds__(256) void k_Tsplit(const float* __restrict__ src,
                                                float* __restrict__ dst) {
    __shared__ float t[32][33];
    int n0 = blockIdx.x * 32, k0 = blockIdx.y * 32;
    int tx = threadIdx.x, ty = threadIdx.y;
#pragma unroll
    for (int j = 0; j < 4; j++)
        t[ty + 8 * j][tx] = src[(size_t)(k0 + ty + 8 * j) * NN + n0 + tx];
    __syncthreads();
    float2* d2 = (float2*)dst;
#pragma unroll
    for (int j = 0; j < 4; j++) {
        int n = n0 + ty + 8 * j;
        int k = k0 + tx;
        uint32_t hi, lo;
        tf32split(t[tx][ty + 8 * j], hi, lo);
        d2[(size_t)n * KK + k] = make_float2(__uint_as_float(hi), __uint_as_float(lo));
    }
}

// ---------- split-K pooler GEMM: high-MLP variant ----------
// grid (FH/256=4, KSPLIT=32), block 256: 64 col-lanes x 4 row-groups of 16 rows
__global__ __launch_bounds__(256) void k_pp_part(const float* __restrict__ pooler,
                                                 const float* __restrict__ W1) {
    constexpr int KC = H_ / KSPLIT;      // 24
    __shared__ float a[B_][KC];
    const int ks = blockIdx.y, k0 = ks * KC;
    const int colBase = blockIdx.x * 256;
    const int tid = threadIdx.x;
    const int tx = tid & 63;             // 64 col-lanes, 4 cols each
    const int ty = tid >> 6;             // 4 row-groups, 16 rows each

    for (int idx = tid; idx < B_ * KC; idx += 256) {
        int row = idx / KC, kk = idx % KC;
        a[row][kk] = pooler[(size_t)row * H_ + k0 + kk];
    }
    __syncthreads();

    const float* wp = W1 + (size_t)H_ * FH_ + (size_t)k0 * FH_ + colBase + tx * 4;
    float acc[16][4];
#pragma unroll
    for (int r = 0; r < 16; r++)
#pragma unroll
        for (int j = 0; j < 4; j++) acc[r][j] = 0.f;

#pragma unroll
    for (int kk = 0; kk < KC; kk++) {
        float4 w = *(const float4*)(wp + (size_t)kk * FH_);
#pragma unroll
        for (int r = 0; r < 16; r++) {
            float av = a[ty * 16 + r][kk];
            acc[r][0] = fmaf(av, w.x, acc[r][0]);
            acc[r][1] = fmaf(av, w.y, acc[r][1]);
            acc[r][2] = fmaf(av, w.z, acc[r][2]);
            acc[r][3] = fmaf(av, w.w, acc[r][3]);
        }
    }
#pragma unroll
    for (int r = 0; r < 16; r++)
        *(float4*)&g_ppp[ks][(size_t)(ty * 16 + r) * FH_ + colBase + tx * 4] =
            make_float4(acc[r][0], acc[r][1], acc[r][2], acc[r][3]);
}

// fixed-order reduce of KSPLIT partials + b1 -> g_pp
__global__ __launch_bounds__(256) void k_pp_reduce(const float* __restrict__ b1) {
    int i4 = blockIdx.x * 256 + threadIdx.x;          // float4 index
    int col = (i4 * 4) % FH_;
    float4 s = make_float4(0.f, 0.f, 0.f, 0.f);
#pragma unroll
    for (int ks = 0; ks < KSPLIT; ks++) {
        float4 v = *(const float4*)&g_ppp[ks][(size_t)i4 * 4];
        s.x += v.x; s.y += v.y; s.z += v.z; s.w += v.w;
    }
    float4 bb = *(const float4*)&b1[col];
    s.x += bb.x; s.y += bb.y; s.z += bb.z; s.w += bb.w;
    *(float4*)&g_pp[(size_t)i4 * 4] = s;
}

// ======================= tf32x3 mma.sync GEMM (B pre-split) =======================
// MODE 0: h1[2048,1024] = gather(te) @ W1Ts^T + pp[b]   (BM=128,BN=128,K=768)
// MODE 1: h2[2048, 512] = h1 @ W2Ts^T + b2              (BM=128,BN=64, K=1024)
// A: fp32, split inline.  B: interleaved (hi,lo) float2 planes, no inline split.
template<int MODE>
__global__ __launch_bounds__(256) void mma_gemm(
    const float* __restrict__ Asrc, const int* __restrict__ rowoff,
    const float* __restrict__ Bsrc, float* __restrict__ Cout,
    const float* __restrict__ addv)
{
    constexpr int BM  = 128;
    constexpr int BN  = (MODE == 0) ? 128 : 64;
    constexpr int K   = (MODE == 0) ? H_ : FH_;
    constexpr int NIT = K / 32;
    constexpr int LDO = (MODE == 0) ? FH_ : (FH_ / 2);
    constexpr int MT  = (MODE == 0) ? 2 : 1;
    constexpr int BCH2 = BN / 16;               // B CP16 per thread (8 or 4)
    constexpr int ABUF = 128 * 36;              // floats per A buffer
    constexpr int BBUF2 = BN * 36;              // float2 per B buffer

    extern __shared__ float sm[];
    float*  AsB = sm;                           // [2][ABUF] fp32
    float2* BsB = (float2*)(sm + 2 * ABUF);     // [2][BBUF2] (hi,lo)

    const int tid = threadIdx.x, wid = tid >> 5, lane = tid & 31;
    const int rowBase = blockIdx.y * BM, colBase = blockIdx.x * BN;
    const int warpRow = (MODE == 0) ? (wid & 3) * 32 : wid * 16;
    const int warpCol = (MODE == 0) ? (wid >> 2) * 64 : 0;

    // A staging: 128 rows x 32 k fp32 -> 1024 CP16, 4/thread
    const float* aptr[4];
    int arow[4];
#pragma unroll
    for (int j = 0; j < 4; j++) {
        int r = (tid >> 3) + j * 32;
        arow[j] = r;
        if (MODE == 0) aptr[j] = Asrc + rowoff[rowBase + r];
        else           aptr[j] = Asrc + (size_t)(rowBase + r) * K;
    }
    const int acol = (tid & 7) * 4;

    // B staging: BN rows x 32 k float2 -> BN*16 CP16, BCH2/thread
    const float2* Bsrc2 = (const float2*)Bsrc;
    const float2* bptr[8];
    int bc2[8];
#pragma unroll
    for (int j = 0; j < BCH2; j++) {
        int ci = tid + j * 256;
        int br = ci >> 4;
        bc2[j] = (ci & 15) * 2;
        bptr[j] = Bsrc2 + (size_t)(colBase + br) * K;
    }
    const uint32_t smA = smem_u32(AsB), smB = smem_u32(BsB);

    float acc[MT][8][4];
#pragma unroll
    for (int mt = 0; mt < MT; mt++)
#pragma unroll
        for (int nt = 0; nt < 8; nt++)
#pragma unroll
            for (int e = 0; e < 4; e++) acc[mt][nt][e] = 0.f;

#define STAGE(buf, k0) do { \
    uint32_t sa = smA + (buf) * (ABUF * 4); \
    _Pragma("unroll") \
    for (int j = 0; j < 4; j++) \
        CP16(sa + (uint32_t)(arow[j] * 36 + acol) * 4, aptr[j] + (k0) + acol); \
    uint32_t sbp = smB + (buf) * (BBUF2 * 8); \
    _Pragma("unroll") \
    for (int j = 0; j < BCH2; j++) { \
        int ci = tid + j * 256; int br = ci >> 4; \
        CP16(sbp + (uint32_t)(br * 36 + bc2[j]) * 8, bptr[j] + (k0) + bc2[j]); \
    } \
    CP_COMMIT(); \
} while (0)

    STAGE(0, 0);
    for (int it = 0; it < NIT; ++it) {
        if (it + 1 < NIT) { STAGE((it + 1) & 1, (it + 1) * 32); CP_WAIT1(); }
        else              { CP_WAIT0(); }
        __syncthreads();
        const float*  As  = AsB + (it & 1) * ABUF;
        const float2* Bs2 = BsB + (it & 1) * BBUF2;
#pragma unroll
        for (int ks = 0; ks < 4; ks++) {
            uint32_t af[MT][4][2];
#pragma unroll
            for (int mt = 0; mt < MT; mt++) {
                int r0 = warpRow + mt * 16 + (lane >> 2);
                int c  = ks * 8 + (lane & 3);
                tf32split(As[r0 * 36 + c],           af[mt][0][0], af[mt][0][1]);
                tf32split(As[(r0 + 8) * 36 + c],     af[mt][1][0], af[mt][1][1]);
                tf32split(As[r0 * 36 + c + 4],       af[mt][2][0], af[mt][2][1]);
                tf32split(As[(r0 + 8) * 36 + c + 4], af[mt][3][0], af[mt][3][1]);
            }
#pragma unroll
            for (int nt = 0; nt < 8; nt++) {
                int n0 = warpCol + nt * 8 + (lane >> 2);
                int c  = ks * 8 + (lane & 3);
                float2 f0 = Bs2[n0 * 36 + c];
                float2 f1 = Bs2[n0 * 36 + c + 4];
                uint32_t bh[2] = { __float_as_uint(f0.x), __float_as_uint(f1.x) };
                uint32_t bl[2] = { __float_as_uint(f0.y), __float_as_uint(f1.y) };
#pragma unroll
                for (int mt = 0; mt < MT; mt++) {
                    uint32_t ah[4] = { af[mt][0][0], af[mt][1][0], af[mt][2][0], af[mt][3][0] };
                    uint32_t al[4] = { af[mt][0][1], af[mt][1][1], af[mt][2][1], af[mt][3][1] };
                    mma_tf32(acc[mt][nt], ah, bh);   // a0*b0
                    mma_tf32(acc[mt][nt], al, bh);   // a1*b0
                    mma_tf32(acc[mt][nt], ah, bl);   // a0*b1
                }
            }
        }
        __syncthreads();
    }
#undef STAGE

    // epilogue: D frag -> global (+ pp or bias)
#pragma unroll
    for (int mt = 0; mt < MT; mt++) {
#pragma unroll
        for (int nt = 0; nt < 8; nt++) {
            int r0 = rowBase + warpRow + mt * 16 + (lane >> 2);
            int c  = colBase + warpCol + nt * 8 + (lane & 3) * 2;
            float2 v0 = make_float2(acc[mt][nt][0], acc[mt][nt][1]);
            float2 v1 = make_float2(acc[mt][nt][2], acc[mt][nt][3]);
            if (MODE == 0) {
                float2 p0 = *(const float2*)&addv[(size_t)(r0 >> 5) * FH_ + c];
                float2 p1 = *(const float2*)&addv[(size_t)((r0 + 8) >> 5) * FH_ + c];
                v0.x += p0.x; v0.y += p0.y; v1.x += p1.x; v1.y += p1.y;
            } else {
                float2 bb = *(const float2*)&addv[c];
                v0.x += bb.x; v0.y += bb.y; v1.x += bb.x; v1.y += bb.y;
            }
            *(float2*)&Cout[(size_t)r0 * LDO + c]       = v0;
            *(float2*)&Cout[(size_t)(r0 + 8) * LDO + c] = v1;
        }
    }
}

// ======================= loss kernels =======================
__global__ __launch_bounds__(256)
void k_loss(const float* __restrict__ W3, const float* __restrict__ b3,
            const float* __restrict__ labels)
{
    const int warpId = threadIdx.x >> 5;
    const int lane   = threadIdx.x & 31;
    const int r = blockIdx.x * 8 + warpId;
    const float* h2row = g_h2 + (size_t)r * (FH_ / 2);
    const bool active = (lane < L_);

    float acc = 0.f;
#pragma unroll 4
    for (int kb = 0; kb < (FH_ / 2) / 32; kb++) {
        float v = h2row[kb * 32 + lane];
#pragma unroll
        for (int j = 0; j < 32; j++) {
            float a = __shfl_sync(0xffffffffu, v, j);
            float w = active ? W3[(kb * 32 + j) * L_ + lane] : 0.f;
            acc = fmaf(a, w, acc);
        }
    }
    float x = acc + (active ? b3[lane] : 0.f);
    float y = active ? labels[(size_t)r * L_ + lane] : -1.0f;

    unsigned ball_bin  = __ballot_sync(0xffffffffu, active && (x > 0.f));
    unsigned ball_one  = __ballot_sync(0xffffffffu, active && (y > 0.5f));
    unsigned ball_real = __ballot_sync(0xffffffffu, active && (y != -1.0f));

    float sp  = fmaxf(x, 0.f) + log1pf(expf(-fabsf(x)));
    float bce = active ? (sp - x * y) : 0.f;
#pragma unroll
    for (int o = 16; o; o >>= 1) bce += __shfl_xor_sync(0xffffffffu, bce, o);

    __shared__ float sml[8][5];
    if (lane == 0) {
        float mf = (ball_real != 0u) ? 1.f : 0.f;
        int co = __popc(ball_bin);
        int cl = __popc(ball_one);
        float cd = (float)(co - cl);
        bool eq = (mf != 0.f) && (co == 1) && (cl == 1);
        float pd = eq ? (float)(__ffs(ball_bin) - __ffs(ball_one)) : 0.f;
        sml[warpId][0] = mf * bce;
        sml[warpId][1] = mf;
        sml[warpId][2] = mf * cd * cd;
        sml[warpId][3] = pd * pd;
        sml[warpId][4] = eq ? 1.f : 0.f;
    }
    __syncthreads();
    if (threadIdx.x < 5) {
        float s = 0.f;
        for (int w = 0; w < 8; w++) s += sml[w][threadIdx.x];
        g_part[blockIdx.x * 5 + threadIdx.x] = s;
    }
}

__global__ __launch_bounds__(256)
void k_final(float* __restrict__ out, int out_size)
{
    __shared__ float smf[256][5];
    int t = threadIdx.x;
    for (int c = 0; c < 5; c++) smf[t][c] = g_part[t * 5 + c];
    __syncthreads();
    for (int s = 128; s > 0; s >>= 1) {
        if (t < s)
            for (int c = 0; c < 5; c++) smf[t][c] += smf[t + s][c];
        __syncthreads();
    }
    if (t == 0) {
        float bce_loss   = smf[0][0] / (smf[0][1] * (float)L_);
        float count_loss = smf[0][2] / (float)MROWS;
        float pos_loss   = (smf[0][4] > 0.f) ? (smf[0][3] / smf[0][4]) : 0.f;
        float loss = bce_loss + 10.f * count_loss + 5.f * pos_loss;
        for (int i = 0; i < out_size; i++) out[i] = loss;
    }
}

// ======================= launch =======================
extern "C" void kernel_launch(void* const* d_in, const int* in_sizes, int n_in,
                              void* d_out, int out_size)
{
    const float* te   = (const float*)d_in[0];
    const float* pool = (const float*)d_in[1];
    const int*   pos  = (const int*)  d_in[2];
    const float* lab  = (const float*)d_in[3];
    const float* W1   = (const float*)d_in[4];
    const float* b1   = (const float*)d_in[5];
    const float* W2   = (const float*)d_in[6];
    const float* b2   = (const float*)d_in[7];
    const float* W3   = (const float*)d_in[8];
    const float* b3   = (const float*)d_in[9];

    float *w1ts, *w2ts, *h1, *h2, *pp;
    int* rowoff;
    cudaGetSymbolAddress((void**)&w1ts,   g_W1Ts);
    cudaGetSymbolAddress((void**)&w2ts,   g_W2Ts);
    cudaGetSymbolAddress((void**)&h1,     g_h1);
    cudaGetSymbolAddress((void**)&h2,     g_h2);
    cudaGetSymbolAddress((void**)&pp,     g_pp);
    cudaGetSymbolAddress((void**)&rowoff, g_rowoff);

    const int SM0 = (2 * 128 * 36) * 4 + (2 * 128 * 36) * 8;   // 110592
    const int SM1 = (2 * 128 * 36) * 4 + (2 * 64 * 36) * 8;    //  73728
    cudaFuncSetAttribute(mma_gemm<0>, cudaFuncAttributeMaxDynamicSharedMemorySize, SM0);
    cudaFuncSetAttribute(mma_gemm<1>, cudaFuncAttributeMaxDynamicSharedMemorySize, SM1);

    // pre-passes
    k_rowoff<<<(MROWS + 255) / 256, 256>>>(pos);
    k_Tsplit<H_, FH_><<<dim3(FH_ / 32, H_ / 32), dim3(32, 8)>>>(W1, w1ts);
    k_Tsplit<FH_, FH_ / 2><<<dim3((FH_ / 2) / 32, FH_ / 32), dim3(32, 8)>>>(W2, w2ts);
    k_pp_part<<<dim3(FH_ / 256, KSPLIT), 256>>>(pool, W1);
    k_pp_reduce<<<(B_ * FH_ / 4) / 256, 256>>>(b1);

    // tensor-core GEMMs (tf32x3 emulated fp32)
    mma_gemm<0><<<dim3(FH_ / 128, MROWS / 128), 256, SM0>>>(te, rowoff, w1ts, h1, pp);
    mma_gemm<1><<<dim3((FH_ / 2) / 64, MROWS / 128), 256, SM1>>>(h1, nullptr, w2ts, h2, b2);

    // loss + reduce
    k_loss<<<MROWS / 8, 256>>>(W3, b3, lab);
    k_final<<<1, 256>>>((float*)d_out, out_size);
}

// round 6
// speedup vs baseline: 4.0830x; 1.4354x over previous
#include <cuda_runtime.h>
#include <cuda_fp16.h>
#include <math.h>
#include <stdint.h>

#define B_   64
#define S_   512
#define P_   32
#define L_   30
#define H_   768
#define FH_  1024
#define MROWS (B_*P_)   // 2048
#define KP   32         // pp partial planes

// ======================= device scratch (no allocation) =======================
__device__ __half g_W1h[FH_ * H_];          // W1[:768]^T hi plane [1024,768]
__device__ __half g_W1l[FH_ * H_];          // lo plane
__device__ __half g_W2h[(FH_/2) * FH_];     // W2^T hi plane [512,1024]
__device__ __half g_W2l[(FH_/2) * FH_];     // lo plane
__device__ float g_h1[MROWS * FH_];         // [2048,1024] fp32
__device__ float g_h2[MROWS * (FH_/2)];     // [2048,512]
__device__ float g_pp[B_ * FH_];            // pooler@W1[768:]+b1
__device__ float g_ppp[KP][B_ * FH_];       // split-K partials
__device__ float g_part[256 * 5];

// ======================= helpers =======================
__device__ __forceinline__ uint32_t smem_u32(const void* p) {
    uint32_t a;
    asm("{ .reg .u64 t; cvta.to.shared.u64 t, %1; cvt.u32.u64 %0, t; }"
        : "=r"(a) : "l"(p));
    return a;
}
#define CP16(dst_u32, src_ptr) \
    asm volatile("cp.async.cg.shared.global [%0], [%1], 16;" \
        :: "r"(dst_u32), "l"(src_ptr))
#define CP_COMMIT() asm volatile("cp.async.commit_group;")
#define CP_WAIT1()  asm volatile("cp.async.wait_group 1;")
#define CP_WAIT0()  asm volatile("cp.async.wait_group 0;")

// split float2 -> packed half2 hi + half2 lo
__device__ __forceinline__ void f2h_split(float2 x, uint32_t& hi, uint32_t& lo) {
    __half2 h = __float22half2_rn(x);
    float2 hf = __half22float2(h);
    __half2 l = __float22half2_rn(make_float2(x.x - hf.x, x.y - hf.y));
    hi = *reinterpret_cast<uint32_t*>(&h);
    lo = *reinterpret_cast<uint32_t*>(&l);
}

__device__ __forceinline__ void mma_f16(float* d, const uint32_t* a,
                                        uint32_t b0, uint32_t b1) {
    asm volatile(
        "mma.sync.aligned.m16n8k16.row.col.f32.f16.f16.f32 "
        "{%0,%1,%2,%3}, {%4,%5,%6,%7}, {%8,%9}, {%0,%1,%2,%3};"
        : "+f"(d[0]), "+f"(d[1]), "+f"(d[2]), "+f"(d[3])
        : "r"(a[0]), "r"(a[1]), "r"(a[2]), "r"(a[3]), "r"(b0), "r"(b1));
}

// ======================= pre-pass kernels =======================
// transpose + fp16-split: src[KK,NN] -> hi/lo half planes at [NN,KK]
template<int KK, int NN>
__global__ __launch_bounds__(256) void k_Tsplit(const float* __restrict__ src,
                                                __half* __restrict__ dh,
                                                __half* __restrict__ dl) {
    __shared__ float t[32][33];
    int n0 = blockIdx.x * 32, k0 = blockIdx.y * 32;
    int tx = threadIdx.x, ty = threadIdx.y;
#pragma unroll
    for (int j = 0; j < 4; j++)
        t[ty + 8 * j][tx] = src[(size_t)(k0 + ty + 8 * j) * NN + n0 + tx];
    __syncthreads();
#pragma unroll
    for (int j = 0; j < 4; j++) {
        int n = n0 + ty + 8 * j;
        int k = k0 + tx;
        float x = t[tx][ty + 8 * j];
        __half h = __float2half_rn(x);
        __half l = __float2half_rn(x - __half2float(h));
        dh[(size_t)n * KK + k] = h;
        dl[(size_t)n * KK + k] = l;
    }
}

// ---------- split-K pooler GEMM, zero-redundancy loads ----------
// grid (FH/128=8, 16), block 256: thread = 1 col x 64 rows, ky halves K chunk
__global__ __launch_bounds__(256) void k_pp_part(const float* __restrict__ pooler,
                                                 const float* __restrict__ W1) {
    __shared__ float a[B_][48];
    const int ks = blockIdx.y;
    const int colBase = blockIdx.x * 128;
    const int tid = threadIdx.x;
    const int col = colBase + (tid & 127);
    const int ky = tid >> 7;                 // 0/1

    for (int idx = tid; idx < B_ * 48; idx += 256) {
        int row = idx / 48, kk = idx % 48;
        a[row][kk] = pooler[(size_t)row * H_ + ks * 48 + kk];
    }
    __syncthreads();

    const float* wp = W1 + (size_t)(H_ + ks * 48 + ky * 24) * FH_ + col;
    float acc[B_];
#pragma unroll
    for (int r = 0; r < B_; r++) acc[r] = 0.f;
#pragma unroll
    for (int kk = 0; kk < 24; kk++) {
        float w = wp[(size_t)kk * FH_];
#pragma unroll
        for (int r = 0; r < B_; r++)
            acc[r] = fmaf(a[r][ky * 24 + kk], w, acc[r]);
    }
    float* out = g_ppp[ks * 2 + ky];
#pragma unroll
    for (int r = 0; r < B_; r++)
        out[(size_t)r * FH_ + col] = acc[r];
}

// fixed-order reduce of KP partials + b1 -> g_pp
__global__ __launch_bounds__(256) void k_pp_reduce(const float* __restrict__ b1) {
    int i4 = blockIdx.x * 256 + threadIdx.x;          // float4 index
    int col = (i4 * 4) % FH_;
    float4 s = make_float4(0.f, 0.f, 0.f, 0.f);
#pragma unroll
    for (int ks = 0; ks < KP; ks++) {
        float4 v = *(const float4*)&g_ppp[ks][(size_t)i4 * 4];
        s.x += v.x; s.y += v.y; s.z += v.z; s.w += v.w;
    }
    float4 bb = *(const float4*)&b1[col];
    s.x += bb.x; s.y += bb.y; s.z += bb.z; s.w += bb.w;
    *(float4*)&g_pp[(size_t)i4 * 4] = s;
}

// ======================= fp16x3 mma.sync GEMM (B pre-split) =======================
// MODE 0: h1[2048,1024] = gather(te) @ W1^T + pp[b]   (BM=128,BN=128,K=768)
// MODE 1: h2[2048, 512] = h1 @ W2^T + b2              (BM=128,BN=64, K=1024)
template<int MODE>
__global__ __launch_bounds__(256) void mma_gemm(
    const float* __restrict__ Asrc, const int* __restrict__ pos,
    const __half* __restrict__ Bh, const __half* __restrict__ Bl,
    float* __restrict__ Cout, const float* __restrict__ addv)
{
    constexpr int BM  = 128;
    constexpr int BN  = (MODE == 0) ? 128 : 64;
    constexpr int K   = (MODE == 0) ? H_ : FH_;
    constexpr int NIT = K / 32;
    constexpr int LDO = (MODE == 0) ? FH_ : (FH_ / 2);
    constexpr int MT  = (MODE == 0) ? 2 : 1;
    constexpr int BCH = BN * 8 / 256;            // B CP16 per thread (4 or 2)
    constexpr int ABUF = 128 * 36;               // floats per A buffer
    constexpr int BPLANE = BN * 40;              // halves per plane
    constexpr int BBUFB = 2 * BPLANE * 2;        // bytes per B buffer (2 planes)

    extern __shared__ float sm[];
    float* AsB = sm;                              // [2][ABUF] fp32
    char*  BsBase = (char*)(sm + 2 * ABUF);       // [2][2 planes][BN][40] half

    const int tid = threadIdx.x, wid = tid >> 5, lane = tid & 31;
    const int rowBase = blockIdx.y * BM, colBase = blockIdx.x * BN;
    const int warpRow = (MODE == 0) ? (wid & 3) * 32 : wid * 16;
    const int warpCol = (MODE == 0) ? (wid >> 2) * 64 : 0;

    // A staging: 128 rows x 32 k fp32 -> 1024 CP16, 4/thread (gather inline)
    const float* aptr[4];
    int arow[4];
#pragma unroll
    for (int j = 0; j < 4; j++) {
        int r = (tid >> 3) + j * 32;
        arow[j] = r;
        if (MODE == 0) {
            int gr = rowBase + r;
            aptr[j] = Asrc + ((size_t)(gr >> 5) * S_ + pos[gr]) * H_;
        } else {
            aptr[j] = Asrc + (size_t)(rowBase + r) * K;
        }
    }
    const int acol = (tid & 7) * 4;

    // B staging: BN rows x 2 planes x 4 chunks of 16B
    const __half* bsrc[4];
    uint32_t bsmo[4];
#pragma unroll
    for (int j = 0; j < BCH; j++) {
        int ci = tid + j * 256;
        int plane = ci / (BN * 4);
        int rem = ci % (BN * 4);
        int row = rem >> 2, ch = rem & 3;
        const __half* gp = plane ? Bl : Bh;
        bsrc[j] = gp + (size_t)(colBase + row) * K + ch * 8;
        bsmo[j] = (uint32_t)(plane * BPLANE + row * 40 + ch * 8) * 2;
    }
    const uint32_t smA = smem_u32(AsB), smB = smem_u32(BsBase);

    float acc[MT][8][4];
#pragma unroll
    for (int mt = 0; mt < MT; mt++)
#pragma unroll
        for (int nt = 0; nt < 8; nt++)
#pragma unroll
            for (int e = 0; e < 4; e++) acc[mt][nt][e] = 0.f;

#define STAGE(buf, k0) do { \
    uint32_t sa = smA + (buf) * (ABUF * 4); \
    _Pragma("unroll") \
    for (int j = 0; j < 4; j++) \
        CP16(sa + (uint32_t)(arow[j] * 36 + acol) * 4, aptr[j] + (k0) + acol); \
    uint32_t sbp = smB + (buf) * BBUFB; \
    _Pragma("unroll") \
    for (int j = 0; j < BCH; j++) \
        CP16(sbp + bsmo[j], bsrc[j] + (k0)); \
    CP_COMMIT(); \
} while (0)

    STAGE(0, 0);
    for (int it = 0; it < NIT; ++it) {
        if (it + 1 < NIT) { STAGE((it + 1) & 1, (it + 1) * 32); CP_WAIT1(); }
        else              { CP_WAIT0(); }
        __syncthreads();
        const float*  As  = AsB + (it & 1) * ABUF;
        const __half* BsH = (const __half*)(BsBase + (it & 1) * BBUFB);
        const __half* BsL = BsH + BPLANE;
#pragma unroll
        for (int c16 = 0; c16 < 2; c16++) {
            const int kk = c16 * 16 + (lane & 3) * 2;
            uint32_t ah[MT][4], al[MT][4];
#pragma unroll
            for (int mt = 0; mt < MT; mt++) {
                int r0 = warpRow + mt * 16 + (lane >> 2);
                float2 x0 = *(const float2*)&As[r0 * 36 + kk];
                float2 x1 = *(const float2*)&As[(r0 + 8) * 36 + kk];
                float2 x2 = *(const float2*)&As[r0 * 36 + kk + 8];
                float2 x3 = *(const float2*)&As[(r0 + 8) * 36 + kk + 8];
                f2h_split(x0, ah[mt][0], al[mt][0]);
                f2h_split(x1, ah[mt][1], al[mt][1]);
                f2h_split(x2, ah[mt][2], al[mt][2]);
                f2h_split(x3, ah[mt][3], al[mt][3]);
            }
#pragma unroll
            for (int nt = 0; nt < 8; nt++) {
                int n0 = warpCol + nt * 8 + (lane >> 2);
                uint32_t bh0 = *(const uint32_t*)&BsH[n0 * 40 + kk];
                uint32_t bh1 = *(const uint32_t*)&BsH[n0 * 40 + kk + 8];
                uint32_t bl0 = *(const uint32_t*)&BsL[n0 * 40 + kk];
                uint32_t bl1 = *(const uint32_t*)&BsL[n0 * 40 + kk + 8];
#pragma unroll
                for (int mt = 0; mt < MT; mt++) {
                    mma_f16(acc[mt][nt], ah[mt], bh0, bh1);   // a0*b0
                    mma_f16(acc[mt][nt], al[mt], bh0, bh1);   // a1*b0
                    mma_f16(acc[mt][nt], ah[mt], bl0, bl1);   // a0*b1
                }
            }
        }
        __syncthreads();
    }
#undef STAGE

    // epilogue: D frag -> global (+ pp or bias)
#pragma unroll
    for (int mt = 0; mt < MT; mt++) {
#pragma unroll
        for (int nt = 0; nt < 8; nt++) {
            int r0 = rowBase + warpRow + mt * 16 + (lane >> 2);
            int c  = colBase + warpCol + nt * 8 + (lane & 3) * 2;
            float2 v0 = make_float2(acc[mt][nt][0], acc[mt][nt][1]);
            float2 v1 = make_float2(acc[mt][nt][2], acc[mt][nt][3]);
            if (MODE == 0) {
                float2 p0 = *(const float2*)&addv[(size_t)(r0 >> 5) * FH_ + c];
                float2 p1 = *(const float2*)&addv[(size_t)((r0 + 8) >> 5) * FH_ + c];
                v0.x += p0.x; v0.y += p0.y; v1.x += p1.x; v1.y += p1.y;
            } else {
                float2 bb = *(const float2*)&addv[c];
                v0.x += bb.x; v0.y += bb.y; v1.x += bb.x; v1.y += bb.y;
            }
            *(float2*)&Cout[(size_t)r0 * LDO + c]       = v0;
            *(float2*)&Cout[(size_t)(r0 + 8) * LDO + c] = v1;
        }
    }
}

// ======================= loss kernels =======================
__global__ __launch_bounds__(256)
void k_loss(const float* __restrict__ W3, const float* __restrict__ b3,
            const float* __restrict__ labels)
{
    const int warpId = threadIdx.x >> 5;
    const int lane   = threadIdx.x & 31;
    const int r = blockIdx.x * 8 + warpId;
    const float* h2row = g_h2 + (size_t)r * (FH_ / 2);
    const bool active = (lane < L_);

    float acc = 0.f;
#pragma unroll 4
    for (int kb = 0; kb < (FH_ / 2) / 32; kb++) {
        float v = h2row[kb * 32 + lane];
#pragma unroll
        for (int j = 0; j < 32; j++) {
            float a = __shfl_sync(0xffffffffu, v, j);
            float w = active ? W3[(kb * 32 + j) * L_ + lane] : 0.f;
            acc = fmaf(a, w, acc);
        }
    }
    float x = acc + (active ? b3[lane] : 0.f);
    float y = active ? labels[(size_t)r * L_ + lane] : -1.0f;

    unsigned ball_bin  = __ballot_sync(0xffffffffu, active && (x > 0.f));
    unsigned ball_one  = __ballot_sync(0xffffffffu, active && (y > 0.5f));
    unsigned ball_real = __ballot_sync(0xffffffffu, active && (y != -1.0f));

    float sp  = fmaxf(x, 0.f) + log1pf(expf(-fabsf(x)));
    float bce = active ? (sp - x * y) : 0.f;
#pragma unroll
    for (int o = 16; o; o >>= 1) bce += __shfl_xor_sync(0xffffffffu, bce, o);

    __shared__ float sml[8][5];
    if (lane == 0) {
        float mf = (ball_real != 0u) ? 1.f : 0.f;
        int co = __popc(ball_bin);
        int cl = __popc(ball_one);
        float cd = (float)(co - cl);
        bool eq = (mf != 0.f) && (co == 1) && (cl == 1);
        float pd = eq ? (float)(__ffs(ball_bin) - __ffs(ball_one)) : 0.f;
        sml[warpId][0] = mf * bce;
        sml[warpId][1] = mf;
        sml[warpId][2] = mf * cd * cd;
        sml[warpId][3] = pd * pd;
        sml[warpId][4] = eq ? 1.f : 0.f;
    }
    __syncthreads();
    if (threadIdx.x < 5) {
        float s = 0.f;
        for (int w = 0; w < 8; w++) s += sml[w][threadIdx.x];
        g_part[blockIdx.x * 5 + threadIdx.x] = s;
    }
}

__global__ __launch_bounds__(256)
void k_final(float* __restrict__ out, int out_size)
{
    __shared__ float smf[256][5];
    int t = threadIdx.x;
    for (int c = 0; c < 5; c++) smf[t][c] = g_part[t * 5 + c];
    __syncthreads();
    for (int s = 128; s > 0; s >>= 1) {
        if (t < s)
            for (int c = 0; c < 5; c++) smf[t][c] += smf[t + s][c];
        __syncthreads();
    }
    if (t == 0) {
        float bce_loss   = smf[0][0] / (smf[0][1] * (float)L_);
        float count_loss = smf[0][2] / (float)MROWS;
        float pos_loss   = (smf[0][4] > 0.f) ? (smf[0][3] / smf[0][4]) : 0.f;
        float loss = bce_loss + 10.f * count_loss + 5.f * pos_loss;
        for (int i = 0; i < out_size; i++) out[i] = loss;
    }
}

// ======================= launch =======================
extern "C" void kernel_launch(void* const* d_in, const int* in_sizes, int n_in,
                              void* d_out, int out_size)
{
    const float* te   = (const float*)d_in[0];
    const float* pool = (const float*)d_in[1];
    const int*   pos  = (const int*)  d_in[2];
    const float* lab  = (const float*)d_in[3];
    const float* W1   = (const float*)d_in[4];
    const float* b1   = (const float*)d_in[5];
    const float* W2   = (const float*)d_in[6];
    const float* b2   = (const float*)d_in[7];
    const float* W3   = (const float*)d_in[8];
    const float* b3   = (const float*)d_in[9];

    __half *w1h, *w1l, *w2h, *w2l;
    float *h1, *h2, *pp;
    cudaGetSymbolAddress((void**)&w1h, g_W1h);
    cudaGetSymbolAddress((void**)&w1l, g_W1l);
    cudaGetSymbolAddress((void**)&w2h, g_W2h);
    cudaGetSymbolAddress((void**)&w2l, g_W2l);
    cudaGetSymbolAddress((void**)&h1,  g_h1);
    cudaGetSymbolAddress((void**)&h2,  g_h2);
    cudaGetSymbolAddress((void**)&pp,  g_pp);

    const int SM0 = (2 * 128 * 36) * 4 + 2 * (2 * 128 * 40) * 2;  // 36864+40960=77824
    const int SM1 = (2 * 128 * 36) * 4 + 2 * (2 * 64 * 40) * 2;   // 36864+20480=57344
    cudaFuncSetAttribute(mma_gemm<0>, cudaFuncAttributeMaxDynamicSharedMemorySize, SM0);
    cudaFuncSetAttribute(mma_gemm<1>, cudaFuncAttributeMaxDynamicSharedMemorySize, SM1);

    // pre-passes
    k_Tsplit<H_, FH_><<<dim3(FH_ / 32, H_ / 32), dim3(32, 8)>>>(W1, w1h, w1l);
    k_Tsplit<FH_, FH_ / 2><<<dim3((FH_ / 2) / 32, FH_ / 32), dim3(32, 8)>>>(W2, w2h, w2l);
    k_pp_part<<<dim3(FH_ / 128, 16), 256>>>(pool, W1);
    k_pp_reduce<<<(B_ * FH_ / 4) / 256, 256>>>(b1);

    // tensor-core GEMMs (fp16x3 emulated fp32)
    mma_gemm<0><<<dim3(FH_ / 128, MROWS / 128), 256, SM0>>>(te, pos, w1h, w1l, h1, pp);
    mma_gemm<1><<<dim3((FH_ / 2) / 64, MROWS / 128), 256, SM1>>>(h1, nullptr, w2h, w2l, h2, b2);

    // loss + reduce
    k_loss<<<MROWS / 8, 256>>>(W3, b3, lab);
    k_final<<<1, 256>>>((float*)d_out, out_size);
}